// round 3
// baseline (speedup 1.0000x reference)
#include <cuda_runtime.h>
#include <math.h>

#define BB   128
#define TT   1024
#define DD   128
#define HH   512
#define NHID 1024
#define GRID 128
#define NTHR 256

// ---------------- scratch (static device memory; no allocations) -------------
__device__ float g_h[2][BB * HH];
__device__ float g_c[BB * HH];
__device__ float g_z[BB * HH];
__device__ float g_k[4][BB * HH];
__device__ float g_t1[BB * NHID];
__device__ float g_t2[BB * NHID];
__device__ float g_pred[BB * 5 * HH];
__device__ float g_dec1[BB * 5 * NHID];

__device__ unsigned g_cnt = 0;
__device__ volatile unsigned g_gen = 0;

// ---------------- grid-wide barrier (all 128 blocks co-resident) -------------
__device__ __forceinline__ void gsync() {
    __threadfence();
    __syncthreads();
    if (threadIdx.x == 0) {
        unsigned gen = g_gen;
        if (atomicAdd(&g_cnt, 1u) == GRID - 1) {
            g_cnt = 0;
            __threadfence();
            g_gen = gen + 1;
        } else {
            while (g_gen == gen) { }
        }
    }
    __syncthreads();
    __threadfence();
}

// ---------------- packed f32x2 FMA helpers -----------------------------------
__device__ __forceinline__ void fma2(unsigned long long& acc,
                                     unsigned long long a, unsigned long long b) {
    asm("fma.rn.f32x2 %0, %1, %2, %0;" : "+l"(acc) : "l"(a), "l"(b));
}
__device__ __forceinline__ unsigned long long pack2(float x) {
    unsigned long long r;
    asm("mov.b64 %0, {%1, %1};" : "=l"(r) : "f"(x));
    return r;
}
__device__ __forceinline__ float2 unpack2(unsigned long long v) {
    float2 r;
    asm("mov.b64 {%0, %1}, %2;" : "=f"(r.x), "=f"(r.y) : "l"(v));
    return r;
}

__device__ __forceinline__ float sigmoidf_(float x) { return 1.f / (1.f + expf(-x)); }
__device__ __forceinline__ float eluf_(float x)     { return x > 0.f ? x : expm1f(x); }

// ---------------- core K-block compute (shared for all GEMMs) ----------------
// As[32][34]: [k][row] for 32 rows. Ws[32][64]: [k][col].
// Thread (tx=tid&15, ty=tid>>4) computes rows {ty*2, ty*2+1} x cols {tx*4..+3}.
__device__ __forceinline__ void kblock_fma(
    const float (*As)[34], const float (*Ws)[64], int tx, int ty,
    unsigned long long& a0, unsigned long long& a1,
    unsigned long long& a2, unsigned long long& a3)
{
#pragma unroll
    for (int kk = 0; kk < 32; kk++) {
        float2 av = *(const float2*)&As[kk][ty * 2];
        ulonglong2 wv = *(const ulonglong2*)&Ws[kk][tx * 4];
        unsigned long long ax = pack2(av.x);
        unsigned long long ay = pack2(av.y);
        fma2(a0, ax, wv.x);
        fma2(a1, ax, wv.y);
        fma2(a2, ay, wv.x);
        fma2(a3, ay, wv.y);
    }
}

// Loaders: A-tile (32 rows x 32 k): thread (arow=tid&31, akg=tid>>5) -> float4.
// W-tile (64 cols x 32 k): thread (wn=tid&63, wkg=tid>>6) -> 8 floats.
// Both store patterns are shared-bank conflict-free.

// ---------------- generic GEMM: C[M,N] = act(Aeff @ W[N,K]^T + bias) ----------
// Aeff = A (+ alpha*A2). Tiles: BM=32, BN=64, BK=32. tile-strided over GRID.
template <int ACT, bool HASA2>
__device__ void gemm_dev(const float* __restrict__ A, const float* __restrict__ A2,
                         float alpha, const float* __restrict__ W,
                         const float* __restrict__ bias, float* __restrict__ C,
                         int M, int N, int K, float (*As)[34], float (*Ws)[64])
{
    int tid = threadIdx.x;
    int tx = tid & 15, ty = tid >> 4;
    int arow = tid & 31, akg = tid >> 5;
    int wn = tid & 63, wkg = tid >> 6;
    int ntiles = N >> 6, mtiles = M >> 5;
    int total = ntiles * mtiles;

    for (int tile = blockIdx.x; tile < total; tile += GRID) {
        int n0 = (tile % ntiles) << 6;
        int m0 = (tile / ntiles) << 5;
        const float* Arow  = A + (size_t)(m0 + arow) * K;
        const float* A2row = HASA2 ? (A2 + (size_t)(m0 + arow) * K) : A;
        const float* Wrow  = W + (size_t)(n0 + wn) * K;

        unsigned long long a0 = 0, a1 = 0, a2 = 0, a3 = 0;
        for (int kb = 0; kb < K; kb += 32) {
            float4 av = *(const float4*)(Arow + kb + akg * 4);
            if (HASA2) {
                float4 a2v = *(const float4*)(A2row + kb + akg * 4);
                av.x = fmaf(alpha, a2v.x, av.x);
                av.y = fmaf(alpha, a2v.y, av.y);
                av.z = fmaf(alpha, a2v.z, av.z);
                av.w = fmaf(alpha, a2v.w, av.w);
            }
            As[akg * 4 + 0][arow] = av.x;
            As[akg * 4 + 1][arow] = av.y;
            As[akg * 4 + 2][arow] = av.z;
            As[akg * 4 + 3][arow] = av.w;

            float4 w0 = *(const float4*)(Wrow + kb + wkg * 8);
            float4 w1 = *(const float4*)(Wrow + kb + wkg * 8 + 4);
            Ws[wkg * 8 + 0][wn] = w0.x; Ws[wkg * 8 + 1][wn] = w0.y;
            Ws[wkg * 8 + 2][wn] = w0.z; Ws[wkg * 8 + 3][wn] = w0.w;
            Ws[wkg * 8 + 4][wn] = w1.x; Ws[wkg * 8 + 5][wn] = w1.y;
            Ws[wkg * 8 + 6][wn] = w1.z; Ws[wkg * 8 + 7][wn] = w1.w;
            __syncthreads();
            kblock_fma(As, Ws, tx, ty, a0, a1, a2, a3);
            __syncthreads();
        }

        float4 bv = *(const float4*)(bias + n0 + tx * 4);
        float2 r0a = unpack2(a0), r0b = unpack2(a1);
        float2 r1a = unpack2(a2), r1b = unpack2(a3);
        float4 o0, o1;
        o0.x = r0a.x + bv.x; o0.y = r0a.y + bv.y; o0.z = r0b.x + bv.z; o0.w = r0b.y + bv.w;
        o1.x = r1a.x + bv.x; o1.y = r1a.y + bv.y; o1.z = r1b.x + bv.z; o1.w = r1b.y + bv.w;
        if (ACT == 1) {
            o0.x = eluf_(o0.x); o0.y = eluf_(o0.y); o0.z = eluf_(o0.z); o0.w = eluf_(o0.w);
            o1.x = eluf_(o1.x); o1.y = eluf_(o1.y); o1.z = eluf_(o1.z); o1.w = eluf_(o1.w);
        }
        if (ACT == 2) {
            o0.x = fmaxf(o0.x, 0.f); o0.y = fmaxf(o0.y, 0.f);
            o0.z = fmaxf(o0.z, 0.f); o0.w = fmaxf(o0.w, 0.f);
            o1.x = fmaxf(o1.x, 0.f); o1.y = fmaxf(o1.y, 0.f);
            o1.z = fmaxf(o1.z, 0.f); o1.w = fmaxf(o1.w, 0.f);
        }
        *(float4*)(C + (size_t)(m0 + ty * 2) * N + n0 + tx * 4) = o0;
        *(float4*)(C + (size_t)(m0 + ty * 2 + 1) * N + n0 + tx * 4) = o1;
    }
}

// ---------------- fused LSTM step (one tile per block, 128 tiles) ------------
// Block b: htile = b&31 (16 hidden units), mtile = b>>5 (32 batch rows).
// Columns wn in [0,64): gate g = wn>>4, unit j = wn&15 -> W row g*512 + h0 + j.
__device__ void lstm_step_dev(const float* __restrict__ x,
                              const float* __restrict__ Wih,
                              const float* __restrict__ Whh,
                              const float* __restrict__ bih,
                              const float* __restrict__ bhh,
                              const float* __restrict__ hin,
                              float* __restrict__ hout, int t,
                              float (*As)[34], float (*Ws)[64], float (*Gs)[64])
{
    int tid = threadIdx.x;
    int tx = tid & 15, ty = tid >> 4;
    int arow = tid & 31, akg = tid >> 5;
    int wn = tid & 63, wkg = tid >> 6;
    int h0 = (blockIdx.x & 31) * 16;
    int m0 = (blockIdx.x >> 5) * 32;
    int wcol = (wn >> 4) * HH + h0 + (wn & 15);

    unsigned long long a0 = 0, a1 = 0, a2 = 0, a3 = 0;

    // part 1: x_t @ W_ih^T (K = 128)
    {
        const float* Arow = x + ((size_t)(m0 + arow) * TT + t) * DD;
        const float* Wrow = Wih + (size_t)wcol * DD;
        for (int kb = 0; kb < DD; kb += 32) {
            float4 av = *(const float4*)(Arow + kb + akg * 4);
            As[akg * 4 + 0][arow] = av.x; As[akg * 4 + 1][arow] = av.y;
            As[akg * 4 + 2][arow] = av.z; As[akg * 4 + 3][arow] = av.w;
            float4 w0 = *(const float4*)(Wrow + kb + wkg * 8);
            float4 w1 = *(const float4*)(Wrow + kb + wkg * 8 + 4);
            Ws[wkg * 8 + 0][wn] = w0.x; Ws[wkg * 8 + 1][wn] = w0.y;
            Ws[wkg * 8 + 2][wn] = w0.z; Ws[wkg * 8 + 3][wn] = w0.w;
            Ws[wkg * 8 + 4][wn] = w1.x; Ws[wkg * 8 + 5][wn] = w1.y;
            Ws[wkg * 8 + 6][wn] = w1.z; Ws[wkg * 8 + 7][wn] = w1.w;
            __syncthreads();
            kblock_fma(As, Ws, tx, ty, a0, a1, a2, a3);
            __syncthreads();
        }
    }
    // part 2: h @ W_hh^T (K = 512)
    {
        const float* Arow = hin + (size_t)(m0 + arow) * HH;
        const float* Wrow = Whh + (size_t)wcol * HH;
        for (int kb = 0; kb < HH; kb += 32) {
            float4 av = *(const float4*)(Arow + kb + akg * 4);
            As[akg * 4 + 0][arow] = av.x; As[akg * 4 + 1][arow] = av.y;
            As[akg * 4 + 2][arow] = av.z; As[akg * 4 + 3][arow] = av.w;
            float4 w0 = *(const float4*)(Wrow + kb + wkg * 8);
            float4 w1 = *(const float4*)(Wrow + kb + wkg * 8 + 4);
            Ws[wkg * 8 + 0][wn] = w0.x; Ws[wkg * 8 + 1][wn] = w0.y;
            Ws[wkg * 8 + 2][wn] = w0.z; Ws[wkg * 8 + 3][wn] = w0.w;
            Ws[wkg * 8 + 4][wn] = w1.x; Ws[wkg * 8 + 5][wn] = w1.y;
            Ws[wkg * 8 + 6][wn] = w1.z; Ws[wkg * 8 + 7][wn] = w1.w;
            __syncthreads();
            kblock_fma(As, Ws, tx, ty, a0, a1, a2, a3);
            __syncthreads();
        }
    }

    // gates -> shared with bias
    {
        int g = (tx * 4) >> 4;
        int j0 = (tx * 4) & 15;
        int bbase = g * HH + h0 + j0;
        float4 bi = *(const float4*)(bih + bbase);
        float4 bh = *(const float4*)(bhh + bbase);
        float2 r0a = unpack2(a0), r0b = unpack2(a1);
        float2 r1a = unpack2(a2), r1b = unpack2(a3);
        float4 g0, g1;
        g0.x = r0a.x + bi.x + bh.x; g0.y = r0a.y + bi.y + bh.y;
        g0.z = r0b.x + bi.z + bh.z; g0.w = r0b.y + bi.w + bh.w;
        g1.x = r1a.x + bi.x + bh.x; g1.y = r1a.y + bi.y + bh.y;
        g1.z = r1b.x + bi.z + bh.z; g1.w = r1b.y + bi.w + bh.w;
        *(float4*)&Gs[ty * 2][tx * 4]     = g0;
        *(float4*)&Gs[ty * 2 + 1][tx * 4] = g1;
    }
    __syncthreads();

    // elementwise c/h update: 512 elems, 2 per thread
#pragma unroll
    for (int q = 0; q < 2; q++) {
        int il = q * NTHR + tid;
        int rr = il >> 4, jj = il & 15;
        float iv = sigmoidf_(Gs[rr][jj]);
        float fv = sigmoidf_(Gs[rr][16 + jj]);
        float gv = tanhf(Gs[rr][32 + jj]);
        float ov = sigmoidf_(Gs[rr][48 + jj]);
        int idx = (m0 + rr) * HH + h0 + jj;
        float cn = fv * g_c[idx] + iv * gv;
        g_c[idx] = cn;
        hout[idx] = ov * tanhf(cn);
    }
    __syncthreads();
}

// ---------------- mega persistent kernel (single graph node) -----------------
__global__ __launch_bounds__(NTHR) void mega_kernel(
    const float* __restrict__ x,
    const float* __restrict__ Wih, const float* __restrict__ Whh,
    const float* __restrict__ bih, const float* __restrict__ bhh,
    const float* __restrict__ ow1, const float* __restrict__ ob1,
    const float* __restrict__ ow2, const float* __restrict__ ob2,
    const float* __restrict__ ow3, const float* __restrict__ ob3,
    const float* __restrict__ dw1, const float* __restrict__ db1,
    const float* __restrict__ dw2, const float* __restrict__ db2,
    float* __restrict__ out)
{
    __shared__ float As[32][34];
    __shared__ float Ws[32][64];
    __shared__ float Gs[32][64];

    int tid = threadIdx.x;
    int gidx = blockIdx.x * NTHR + tid;   // 32768 threads, 2 elems each of 65536

    // ---- init h0, c0 ----
    g_h[0][gidx] = 0.f; g_h[0][gidx + GRID * NTHR] = 0.f;
    g_c[gidx] = 0.f;    g_c[gidx + GRID * NTHR] = 0.f;
    gsync();

    // ---- LSTM encoder: 1024 steps ----
    for (int t = 0; t < TT; t++) {
        const float* hin = (t & 1) ? g_h[1] : g_h[0];
        float* hout      = (t & 1) ? g_h[0] : g_h[1];
        lstm_step_dev(x, Wih, Whh, bih, bhh, hin, hout, t, As, Ws, Gs);
        gsync();
    }

    // ---- z0 = c_n; pred slot 0 ----
#pragma unroll
    for (int q = 0; q < 2; q++) {
        int e = gidx + q * GRID * NTHR;
        float v = g_c[e];
        g_z[e] = v;
        int b = e >> 9, h = e & 511;
        g_pred[(b * 5) * HH + h] = v;
    }
    gsync();

    // ---- latent ODE: 32 RK4 substeps ----
    const double dtd = (5.0 / 60.0) / 8.0;
    const float dtf  = (float)dtd;
    const float half = (float)(0.5 * dtd);
    const float dt6  = (float)(dtd / 6.0);

    for (int step = 0; step < 32; step++) {
        // k1 = f(z)
        gemm_dev<1, false>(g_z, nullptr, 0.f, ow1, ob1, g_t1, BB, NHID, HH, As, Ws); gsync();
        gemm_dev<1, false>(g_t1, nullptr, 0.f, ow2, ob2, g_t2, BB, NHID, NHID, As, Ws); gsync();
        gemm_dev<0, false>(g_t2, nullptr, 0.f, ow3, ob3, g_k[0], BB, HH, NHID, As, Ws); gsync();
        // k2 = f(z + 0.5 dt k1)
        gemm_dev<1, true>(g_z, g_k[0], half, ow1, ob1, g_t1, BB, NHID, HH, As, Ws); gsync();
        gemm_dev<1, false>(g_t1, nullptr, 0.f, ow2, ob2, g_t2, BB, NHID, NHID, As, Ws); gsync();
        gemm_dev<0, false>(g_t2, nullptr, 0.f, ow3, ob3, g_k[1], BB, HH, NHID, As, Ws); gsync();
        // k3 = f(z + 0.5 dt k2)
        gemm_dev<1, true>(g_z, g_k[1], half, ow1, ob1, g_t1, BB, NHID, HH, As, Ws); gsync();
        gemm_dev<1, false>(g_t1, nullptr, 0.f, ow2, ob2, g_t2, BB, NHID, NHID, As, Ws); gsync();
        gemm_dev<0, false>(g_t2, nullptr, 0.f, ow3, ob3, g_k[2], BB, HH, NHID, As, Ws); gsync();
        // k4 = f(z + dt k3)
        gemm_dev<1, true>(g_z, g_k[2], dtf, ow1, ob1, g_t1, BB, NHID, HH, As, Ws); gsync();
        gemm_dev<1, false>(g_t1, nullptr, 0.f, ow2, ob2, g_t2, BB, NHID, NHID, As, Ws); gsync();
        gemm_dev<0, false>(g_t2, nullptr, 0.f, ow3, ob3, g_k[3], BB, HH, NHID, As, Ws); gsync();
        // combine
#pragma unroll
        for (int q = 0; q < 2; q++) {
            int e = gidx + q * GRID * NTHR;
            float z = g_z[e] + dt6 * (g_k[0][e] + 2.f * (g_k[1][e] + g_k[2][e]) + g_k[3][e]);
            g_z[e] = z;
            if ((step & 7) == 7) {
                int b = e >> 9, h = e & 511;
                g_pred[(b * 5 + (step >> 3) + 1) * HH + h] = z;
            }
        }
        gsync();
    }

    // ---- decoder ----
    gemm_dev<2, false>(g_pred, nullptr, 0.f, dw1, db1, g_dec1, BB * 5, NHID, HH, As, Ws);
    gsync();
    gemm_dev<0, false>(g_dec1, nullptr, 0.f, dw2, db2, out, BB * 5, DD, NHID, As, Ws);
}

// ---------------- host side ---------------------------------------------------
extern "C" void kernel_launch(void* const* d_in, const int* in_sizes, int n_in,
                              void* d_out, int out_size)
{
    const float* inputs = (const float*)d_in[0];

    // Locate W_ih robustly: 4*512*128 elems followed by 4*512*512.
    int p = 2;
    for (int i = 1; i + 1 < n_in; i++) {
        if (in_sizes[i] == 4 * HH * DD && in_sizes[i + 1] == 4 * HH * HH) { p = i; break; }
    }
    const float* W_ih  = (const float*)d_in[p + 0];
    const float* W_hh  = (const float*)d_in[p + 1];
    const float* b_ih  = (const float*)d_in[p + 2];
    const float* b_hh  = (const float*)d_in[p + 3];
    const float* ow1 = (const float*)d_in[p + 4];
    const float* ob1 = (const float*)d_in[p + 5];
    const float* ow2 = (const float*)d_in[p + 6];
    const float* ob2 = (const float*)d_in[p + 7];
    const float* ow3 = (const float*)d_in[p + 8];
    const float* ob3 = (const float*)d_in[p + 9];
    const float* dw1 = (const float*)d_in[p + 10];
    const float* db1 = (const float*)d_in[p + 11];
    const float* dw2 = (const float*)d_in[p + 12];
    const float* db2 = (const float*)d_in[p + 13];

    mega_kernel<<<GRID, NTHR>>>(inputs, W_ih, W_hh, b_ih, b_hh,
                                ow1, ob1, ow2, ob2, ow3, ob3,
                                dw1, db1, dw2, db2, (float*)d_out);
}